// round 16
// baseline (speedup 1.0000x reference)
#include <cuda_runtime.h>
#include <cuda_bf16.h>
#include <cstdint>

#define NSEQ 512
#define DFEAT 48
#define DH 96
#define TPB 128

// Factored first-layer projections.
// g_A[b][i][k] = sum_c x[b,i,c]*W1[c,k] + b1[k]
// g_B[b][j][k] = sum_c x[b,j,c]*W1[48+c,k]
__device__ float g_A[4 * NSEQ * DH];
__device__ float g_B[4 * NSEQ * DH];

__global__ void precompute_kernel(const float* __restrict__ x,
                                  const float* __restrict__ W1,
                                  const float* __restrict__ b1) {
    int row = blockIdx.x;            // b*N + i
    __shared__ float sx[DFEAT];
    int t = threadIdx.x;             // 0..95
    if (t < DFEAT) sx[t] = x[row * DFEAT + t];
    __syncthreads();
    float a = b1[t];
    float bb = 0.f;
#pragma unroll
    for (int c = 0; c < DFEAT; c++) {
        float xv = sx[c];
        a  = fmaf(xv, W1[c * DH + t], a);
        bb = fmaf(xv, W1[(DFEAT + c) * DH + t], bb);
    }
    g_A[row * DH + t] = a;
    g_B[row * DH + t] = bb;
}

__device__ __forceinline__ unsigned long long bcast2(float v) {
    unsigned long long r;
    asm("mov.b64 %0, {%1, %1};" : "=l"(r) : "r"(__float_as_uint(v)));
    return r;
}
__device__ __forceinline__ unsigned long long pack2(float lo, float hi) {
    unsigned long long r;
    asm("mov.b64 %0, {%1, %2};" : "=l"(r) : "r"(__float_as_uint(lo)), "r"(__float_as_uint(hi)));
    return r;
}
__device__ __forceinline__ uint32_t totf(float f) {
    uint32_t d;
    asm("cvt.rna.tf32.f32 %0, %1;" : "=r"(d) : "f"(f));
    return d;
}

// Packed-constant bundle for the f32x2 gelu chain (polynomial coefficients
// sign-flipped so q' = -q and E = fma(k*q', e, 1) needs no negate).
struct GC {
    unsigned long long nl, Aa, one2, p5, p4, p3, p2, p1;
};

// Branchless 2x exact-GELU on a packed pair: returns in = x + |x|*erf(|x|/sqrt2)
// = 2*gelu(x). The 0.5 factor is folded into the staged W2. (A-S 7.1.26 erf.)
__device__ __forceinline__ unsigned long long gelu2x2(unsigned long long x2, const GC& C) {
    unsigned long long ax2, xx2, t2, e2p, kd2, k2, q2, kq2, E2, in2;
    asm("and.b64 %0, %1, 0x7FFFFFFF7FFFFFFF;" : "=l"(ax2) : "l"(x2));
    asm("mul.rn.f32x2 %0, %1, %1;" : "=l"(xx2) : "l"(x2));
    asm("mul.rn.f32x2 %0, %1, %2;" : "=l"(t2) : "l"(xx2), "l"(C.nl));
    uint32_t tl, th;
    asm("mov.b64 {%0,%1}, %2;" : "=r"(tl), "=r"(th) : "l"(t2));
    float e0, e1;
    asm("ex2.approx.f32 %0, %1;" : "=f"(e0) : "f"(__uint_as_float(tl)));
    asm("ex2.approx.f32 %0, %1;" : "=f"(e1) : "f"(__uint_as_float(th)));
    e2p = pack2(e0, e1);
    asm("fma.rn.f32x2 %0, %1, %2, %3;" : "=l"(kd2) : "l"(ax2), "l"(C.Aa), "l"(C.one2));
    uint32_t kl, kh;
    asm("mov.b64 {%0,%1}, %2;" : "=r"(kl), "=r"(kh) : "l"(kd2));
    float k0f, k1f;
    asm("rcp.approx.f32 %0, %1;" : "=f"(k0f) : "f"(__uint_as_float(kl)));
    asm("rcp.approx.f32 %0, %1;" : "=f"(k1f) : "f"(__uint_as_float(kh)));
    k2 = pack2(k0f, k1f);
    asm("fma.rn.f32x2 %0, %1, %2, %3;" : "=l"(q2) : "l"(k2), "l"(C.p5), "l"(C.p4));
    asm("fma.rn.f32x2 %0, %1, %2, %3;" : "=l"(q2) : "l"(k2), "l"(q2), "l"(C.p3));
    asm("fma.rn.f32x2 %0, %1, %2, %3;" : "=l"(q2) : "l"(k2), "l"(q2), "l"(C.p2));
    asm("fma.rn.f32x2 %0, %1, %2, %3;" : "=l"(q2) : "l"(k2), "l"(q2), "l"(C.p1));
    asm("mul.rn.f32x2 %0, %1, %2;" : "=l"(kq2) : "l"(k2), "l"(q2));   // = -k*q
    asm("fma.rn.f32x2 %0, %1, %2, %3;" : "=l"(E2) : "l"(kq2), "l"(e2p), "l"(C.one2));
    asm("fma.rn.f32x2 %0, %1, %2, %3;" : "=l"(in2) : "l"(ax2), "l"(E2), "l"(x2));
    return in2;
}

__device__ __forceinline__ void hmma_tf32(float* c, uint32_t a0, uint32_t a1,
                                          uint32_t a2, uint32_t a3,
                                          uint32_t b0, uint32_t b1) {
    asm volatile(
        "mma.sync.aligned.m16n8k8.row.col.f32.tf32.tf32.f32 "
        "{%0,%1,%2,%3}, {%4,%5,%6,%7}, {%8,%9}, {%0,%1,%2,%3};"
        : "+f"(c[0]), "+f"(c[1]), "+f"(c[2]), "+f"(c[3])
        : "r"(a0), "r"(a1), "r"(a2), "r"(a3), "r"(b0), "r"(b1));
}

// One CTA per output row (b,i). 4 warps; m16 j-tile t goes to warp t%4.
// k assignment: per kt''=0..5 thread q owns 4 CONTIGUOUS global k's
// 16kt''+4q..+3, covering MMA steps kt=2kt'' (pair .x) and 2kt''+1 (pair .y)
// => one LDG.128 / LDS.128 per row per kt''. gelu packed f32x2 (2x-scaled;
// 0.5 folded into staged W2); A fragments are raw fp32 bits (tf32 truncation);
// acc initialized from permuted smem b2.
__global__ void __launch_bounds__(TPB, 6) pair_kernel(const float* __restrict__ W2,
                                                      const float* __restrict__ b2,
                                                      float* __restrict__ out) {
    const int i = (int)(gridDim.x - 1 - blockIdx.x);   // longest rows first
    const int b = blockIdx.y;
    const int tid = threadIdx.x;
    const int w = tid >> 5;
    const int lane = tid & 31;
    const int q = lane & 3;        // thread within group of 4
    const int r = lane >> 2;       // group id 0..7

    // B fragments: [kt*3+ntp][lane] = { (b0,b1) for nt=2ntp, (b0,b1) for nt=2ntp+1 }
    __shared__ __align__(16) ulonglong2 sB[36 * 32];   // 18 KB
    __shared__ __align__(16) float sA[DH];
    __shared__ __align__(16) float sb2p[DFEAT];        // permuted: [q][2nt+h]
    __shared__ float red_m[4], red_s[4];
    __shared__ __align__(16) float red_o[4][DFEAT];

    // Stage (W2 * 0.5) tf32 B-fragments with the grouped-k mapping:
    // MMA step kt: tile-row q <-> global k0 = 16*(kt>>1) + 4q + 2*(kt&1),
    // tile-row q+4 <-> k0+1.
    for (int s36 = w; s36 < 36; s36 += 4) {
        int kt = s36 / 3, ntp = s36 - kt * 3;
        int k0 = 16 * (kt >> 1) + 4 * q + 2 * (kt & 1);
        int n0 = 16 * ntp + r;
        int n1 = 16 * ntp + 8 + r;
        uint32_t b0a = totf(0.5f * W2[k0 * DFEAT + n0]);
        uint32_t b1a = totf(0.5f * W2[(k0 + 1) * DFEAT + n0]);
        uint32_t b0b = totf(0.5f * W2[k0 * DFEAT + n1]);
        uint32_t b1b = totf(0.5f * W2[(k0 + 1) * DFEAT + n1]);
        ulonglong2 v;
        asm("mov.b64 %0, {%1, %2};" : "=l"(v.x) : "r"(b0a), "r"(b1a));
        asm("mov.b64 %0, {%1, %2};" : "=l"(v.y) : "r"(b0b), "r"(b1b));
        sB[s36 * 32 + lane] = v;
    }
    if (tid < DH) sA[tid] = g_A[(b * NSEQ + i) * DH + tid];
    if (tid < DFEAT) {                 // sb2p[qq*12 + 2nt + h] = b2[8nt + 2qq + h]
        int qq = tid / 12, rem = tid % 12;
        sb2p[tid] = b2[8 * (rem >> 1) + 2 * qq + (rem & 1)];
    }
    __syncthreads();

    GC C;
    C.nl = bcast2(-0.72134752044448170368f);
    C.Aa = bcast2(0.23164408767166038f);
    C.one2 = bcast2(1.0f);
    C.p5 = bcast2(-1.061405429f);
    C.p4 = bcast2(1.453152027f);
    C.p3 = bcast2(-1.421413741f);
    C.p2 = bcast2(0.284496736f);
    C.p1 = bcast2(-0.254829592f);

    const float* __restrict__ Bbase = g_B + b * NSEQ * DH;
    const float4* __restrict__ b2q = (const float4*)(sb2p + q * 12);
    const unsigned full = 0xffffffffu;

    float m = -1e30f, s = 0.f;
    unsigned long long o2[6];
#pragma unroll
    for (int nt = 0; nt < 6; nt++) o2[nt] = 0ull;

    for (int t = w; 16 * t <= i; t += 4) {
        const int j0 = 16 * t;

        float acc[6][4];
        {
            float4 v0 = b2q[0], v1 = b2q[1], v2 = b2q[2];
            acc[0][0] = v0.x; acc[0][1] = v0.y; acc[0][2] = v0.x; acc[0][3] = v0.y;
            acc[1][0] = v0.z; acc[1][1] = v0.w; acc[1][2] = v0.z; acc[1][3] = v0.w;
            acc[2][0] = v1.x; acc[2][1] = v1.y; acc[2][2] = v1.x; acc[2][3] = v1.y;
            acc[3][0] = v1.z; acc[3][1] = v1.w; acc[3][2] = v1.z; acc[3][3] = v1.w;
            acc[4][0] = v2.x; acc[4][1] = v2.y; acc[4][2] = v2.x; acc[4][3] = v2.y;
            acc[5][0] = v2.z; acc[5][1] = v2.w; acc[5][2] = v2.z; acc[5][3] = v2.w;
        }

#pragma unroll
        for (int kt2 = 0; kt2 < 6; kt2++) {
            const int c0 = 16 * kt2 + 4 * q;
            ulonglong2 aP = *(const ulonglong2*)&sA[c0];
            const int ro = (j0 + r) * DH + c0;
            ulonglong2 xA = *(const ulonglong2*)(Bbase + ro);
            ulonglong2 xB = *(const ulonglong2*)(Bbase + ro + 8 * DH);

#pragma unroll
            for (int sub = 0; sub < 2; sub++) {
                unsigned long long aPh = sub ? aP.y : aP.x;
                unsigned long long xAh = sub ? xA.y : xA.x;
                unsigned long long xBh = sub ? xB.y : xB.x;
                unsigned long long pA, pB;
                asm("add.rn.f32x2 %0, %1, %2;" : "=l"(pA) : "l"(aPh), "l"(xAh));
                asm("add.rn.f32x2 %0, %1, %2;" : "=l"(pB) : "l"(aPh), "l"(xBh));
                unsigned long long gA = gelu2x2(pA, C);
                unsigned long long gB = gelu2x2(pB, C);
                uint32_t a0, a2, a1, a3;
                asm("mov.b64 {%0,%1}, %2;" : "=r"(a0), "=r"(a2) : "l"(gA));
                asm("mov.b64 {%0,%1}, %2;" : "=r"(a1), "=r"(a3) : "l"(gB));

                const int kt = 2 * kt2 + sub;
#pragma unroll
                for (int ntp = 0; ntp < 3; ntp++) {
                    ulonglong2 v = sB[(kt * 3 + ntp) * 32 + lane];
                    uint32_t b0a, b1a, b0b, b1b;
                    asm("mov.b64 {%0, %1}, %2;" : "=r"(b0a), "=r"(b1a) : "l"(v.x));
                    asm("mov.b64 {%0, %1}, %2;" : "=r"(b0b), "=r"(b1b) : "l"(v.y));
                    hmma_tf32(acc[2 * ntp],     a0, a1, a2, a3, b0a, b1a);
                    hmma_tf32(acc[2 * ntp + 1], a0, a1, a2, a3, b0b, b1b);
                }
            }
        }

        // ---- epilogue: rows jA=j0+r, jB=j0+r+8 (acc already = p) ----
        unsigned long long nA2 = 0ull, nB2 = 0ull;
#pragma unroll
        for (int nt = 0; nt < 6; nt++) {
            asm("fma.rn.f32x2 %0, %1, %1, %0;" : "+l"(nA2)
                : "l"(pack2(acc[nt][0], acc[nt][1])));
            asm("fma.rn.f32x2 %0, %1, %1, %0;" : "+l"(nB2)
                : "l"(pack2(acc[nt][2], acc[nt][3])));
        }
        unsigned lo, hi;
        asm("mov.b64 {%0, %1}, %2;" : "=r"(lo), "=r"(hi) : "l"(nA2));
        float nA = __uint_as_float(lo) + __uint_as_float(hi);
        asm("mov.b64 {%0, %1}, %2;" : "=r"(lo), "=r"(hi) : "l"(nB2));
        float nB = __uint_as_float(lo) + __uint_as_float(hi);
        nA += __shfl_xor_sync(full, nA, 1, 4);
        nA += __shfl_xor_sync(full, nA, 2, 4);
        nB += __shfl_xor_sync(full, nB, 1, 4);
        nB += __shfl_xor_sync(full, nB, 2, 4);
        const int jA = j0 + r, jB = j0 + r + 8;
        float sqA, sqB;
        asm("sqrt.approx.f32 %0, %1;" : "=f"(sqA) : "f"(nA));
        asm("sqrt.approx.f32 %0, %1;" : "=f"(sqB) : "f"(nB));
        float wA = (jA <= i) ? sqA : -1e30f;
        float wB = (jB <= i) ? sqB : -1e30f;

        float mN = fmaxf(m, fmaxf(wA, wB));
        float c  = __expf(m - mN);
        float eA = __expf(wA - mN);
        float eB = __expf(wB - mN);
        s = s * c + eA + eB;
        m = mN;
        unsigned long long c2 = bcast2(c), eA2 = bcast2(eA), eB2 = bcast2(eB);
#pragma unroll
        for (int nt = 0; nt < 6; nt++) {
            asm("mul.rn.f32x2 %0, %0, %1;" : "+l"(o2[nt]) : "l"(c2));
            asm("fma.rn.f32x2 %0, %1, %2, %0;" : "+l"(o2[nt])
                : "l"(pack2(acc[nt][0], acc[nt][1])), "l"(eA2));
            asm("fma.rn.f32x2 %0, %1, %2, %0;" : "+l"(o2[nt])
                : "l"(pack2(acc[nt][2], acc[nt][3])), "l"(eB2));
        }
    }

    // ---- merge the 8 r-groups within each warp (preserving q feature lanes) ----
#pragma unroll
    for (int off = 4; off <= 16; off <<= 1) {
        float mo = __shfl_xor_sync(full, m, off);
        float so = __shfl_xor_sync(full, s, off);
        float mN = fmaxf(m, mo);
        float fs = __expf(m - mN);
        float fo = __expf(mo - mN);
        s = s * fs + so * fo;
        unsigned long long fs2 = bcast2(fs), fo2 = bcast2(fo);
#pragma unroll
        for (int nt = 0; nt < 6; nt++) {
            unsigned long long t = __shfl_xor_sync(full, o2[nt], off);
            asm("mul.rn.f32x2 %0, %0, %1;"     : "+l"(o2[nt]) : "l"(fs2));
            asm("fma.rn.f32x2 %0, %1, %2, %0;" : "+l"(o2[nt]) : "l"(t), "l"(fo2));
        }
        m = mN;
    }

    if (lane < 4) {                    // lanes 0..3 carry q=0..3 warp results
        if (lane == 0) { red_m[w] = m; red_s[w] = s; }
#pragma unroll
        for (int nt = 0; nt < 6; nt++) {
            unsigned lo, hi;
            asm("mov.b64 {%0, %1}, %2;" : "=r"(lo), "=r"(hi) : "l"(o2[nt]));
            red_o[w][8 * nt + 2 * q]     = __uint_as_float(lo);
            red_o[w][8 * nt + 2 * q + 1] = __uint_as_float(hi);
        }
    }
    __syncthreads();

    if (tid < DFEAT) {
        float M = fmaxf(fmaxf(red_m[0], red_m[1]), fmaxf(red_m[2], red_m[3]));
        float S = 0.f, O = 0.f;
#pragma unroll
        for (int ww = 0; ww < 4; ww++) {
            float f = __expf(red_m[ww] - M);   // 0 for idle warps
            S += red_s[ww] * f;
            O += red_o[ww][tid] * f;
        }
        out[(b * NSEQ + i) * DFEAT + tid] = O / S;
    }
}

extern "C" void kernel_launch(void* const* d_in, const int* in_sizes, int n_in,
                              void* d_out, int out_size) {
    const float* x  = (const float*)d_in[0];
    const float* W1 = (const float*)d_in[1];
    const float* b1 = (const float*)d_in[2];
    const float* W2 = (const float*)d_in[3];
    const float* b2 = (const float*)d_in[4];
    float* out = (float*)d_out;

    precompute_kernel<<<4 * NSEQ, DH>>>(x, W1, b1);
    dim3 grid(NSEQ, 4);
    pair_kernel<<<grid, TPB>>>(W2, b2, out);
}